// round 1
// baseline (speedup 1.0000x reference)
#include <cuda_runtime.h>
#include <math.h>
#include <stdint.h>

#define NN 4096
#define BB 256
#define G  4            // batches per CTA
#define NCTA (BB / G)   // 64 CTAs
#define T  512          // threads per CTA
#define CHUNKS (NN / 4) // 1024 float4 chunks per row

// Scratch (static device globals: allocation-free rule)
__device__ float g_maskT[(size_t)NN * NN]; // maskT[i*N + k] = mask[k*N + i]
__device__ float g_thr[(size_t)BB * NN];   // thr[b*N + i]: decision threshold on x = w_i*acc

// ---------------- XLA-matching sigmoid (logistic -> 0.5 + 0.5*tanh(0.5x),
// tanh = Eigen generic_fast_tanh_float rational approx, as XLA EmitTanh) ----
__device__ __forceinline__ float xla_tanh(float x) {
    float ax = fabsf(x);
    if (ax < 0.0004f) return x;
    float xc = fminf(fmaxf(x, -7.90531110763549805f), 7.90531110763549805f);
    float x2 = xc * xc;
    float p = -2.76076847742355e-16f;
    p = fmaf(x2, p, 2.00018790482477e-13f);
    p = fmaf(x2, p, -8.60467152213735e-11f);
    p = fmaf(x2, p, 5.12229709037114e-08f);
    p = fmaf(x2, p, 1.48572235717979e-05f);
    p = fmaf(x2, p, 6.37261928875436e-04f);
    p = fmaf(x2, p, 4.89352455891786e-03f);
    p = xc * p;
    float q = fmaf(x2, 1.19825839466702e-06f, 1.18534705686654e-04f);
    q = fmaf(x2, q, 2.26843463243900e-03f);
    q = fmaf(x2, q, 4.89352518554385e-03f);
    return p / q;
}
__device__ __forceinline__ float xla_sigmoid(float x) {
    // 0.5*tanh is exact (power of two); single rounding on the add.
    return fmaf(0.5f, xla_tanh(0.5f * x), 0.5f);
}

// ---------------- ordered-int float bisection helpers ----------------
__device__ __forceinline__ unsigned f2o(float f) {
    unsigned b = __float_as_uint(f);
    return (b & 0x80000000u) ? ~b : (b | 0x80000000u);
}
__device__ __forceinline__ float o2f(unsigned o) {
    unsigned b = (o & 0x80000000u) ? (o & 0x7fffffffu) : ~o;
    return __uint_as_float(b);
}

// thr[b*N+i] = smallest fp32 x with (u[b,i] < sigmoid_xla(x)).
// Hot-loop decision becomes: s = (w_i*acc >= thr) ? +1 : -1  (exact).
__global__ void bisect_kernel(const float* __restrict__ u) {
    int idx = blockIdx.x * blockDim.x + threadIdx.x;
    if (idx >= BB * NN) return;
    float uu = u[idx];
    float r;
    if (!(uu < xla_sigmoid(1e30f))) {
        r = INFINITY;              // never sample +1
    } else if (uu < xla_sigmoid(-1e30f)) {
        r = -INFINITY;             // always sample +1
    } else {
        unsigned lo = f2o(-1e30f), hi = f2o(1e30f);
        while (hi - lo > 1u) {
            unsigned mid = lo + ((hi - lo) >> 1);
            if (uu < xla_sigmoid(o2f(mid))) hi = mid; else lo = mid;
        }
        r = o2f(hi);
    }
    g_thr[idx] = r;
}

// ---------------- mask transpose (coalesced both sides) ----------------
__global__ void transpose_kernel(const float* __restrict__ mask) {
    __shared__ float tile[32][33];
    int x = blockIdx.x * 32 + threadIdx.x; // column of mask (= i)
    int y0 = blockIdx.y * 32 + threadIdx.y; // row of mask (= k)
#pragma unroll
    for (int j = 0; j < 32; j += 8)
        tile[threadIdx.y + j][threadIdx.x] = mask[(size_t)(y0 + j) * NN + x];
    __syncthreads();
    int x2 = blockIdx.y * 32 + threadIdx.x; // k
    int y2 = blockIdx.x * 32 + threadIdx.y; // i
#pragma unroll
    for (int j = 0; j < 32; j += 8)
        g_maskT[(size_t)(y2 + j) * NN + x2] = tile[threadIdx.x][threadIdx.y + j];
}

// ---------------- hot autoregressive kernel ----------------
// 64 CTAs, each owns G=4 batch rows. acc in registers: thread t owns float4
// chunks {t, t+T}. One __syncthreads per step; next diagonal value published
// through a parity-double-buffered smem slot. Next mask row prefetched.
__global__ __launch_bounds__(T, 1) void hot_kernel(
    const float* __restrict__ weight, float* __restrict__ out)
{
    __shared__ float sw[NN];
    __shared__ float pub[2][G];
    const int t = threadIdx.x;
    const int bb = blockIdx.x * G;
    for (int idx = t; idx < NN; idx += T) sw[idx] = weight[idx];
    if (t < G) pub[0][t] = 0.0f;

    float4 a0[G], a1[G];
#pragma unroll
    for (int g = 0; g < G; g++) {
        a0[g] = make_float4(0.f, 0.f, 0.f, 0.f);
        a1[g] = make_float4(0.f, 0.f, 0.f, 0.f);
    }
    const int lane = t & 31;
    const int myg = lane & 3;
    const float* __restrict__ thrp = g_thr + (size_t)(bb + myg) * NN;
    __syncthreads();

    // prefetch mask row 0
    const float4* mr4 = (const float4*)g_maskT;
    float4 m0 = __ldg(mr4 + t);
    float4 m1 = __ldg(mr4 + t + T);

    for (int i = 0; i < NN; i++) {
        // --- decision (every warp redundantly; lanes g carry batch g) ---
        float a = pub[i & 1][myg];
        float x = __fmul_rn(sw[i], a);
        float th = __ldg(thrp + i);
        float sv = (x >= th) ? 1.0f : -1.0f;
        float s0 = __shfl_sync(0xffffffffu, sv, 0);
        float s1 = __shfl_sync(0xffffffffu, sv, 1);
        float s2 = __shfl_sync(0xffffffffu, sv, 2);
        float s3 = __shfl_sync(0xffffffffu, sv, 3);
        if (t < G) out[(size_t)(bb + t) * NN + i] = sv; // sample output

        if (i < NN - 1) {
            const int cmin = (i + 1) >> 2;
            if (t >= cmin) {
                a0[0].x = fmaf(s0, m0.x, a0[0].x); a0[0].y = fmaf(s0, m0.y, a0[0].y);
                a0[0].z = fmaf(s0, m0.z, a0[0].z); a0[0].w = fmaf(s0, m0.w, a0[0].w);
                a0[1].x = fmaf(s1, m0.x, a0[1].x); a0[1].y = fmaf(s1, m0.y, a0[1].y);
                a0[1].z = fmaf(s1, m0.z, a0[1].z); a0[1].w = fmaf(s1, m0.w, a0[1].w);
                a0[2].x = fmaf(s2, m0.x, a0[2].x); a0[2].y = fmaf(s2, m0.y, a0[2].y);
                a0[2].z = fmaf(s2, m0.z, a0[2].z); a0[2].w = fmaf(s2, m0.w, a0[2].w);
                a0[3].x = fmaf(s3, m0.x, a0[3].x); a0[3].y = fmaf(s3, m0.y, a0[3].y);
                a0[3].z = fmaf(s3, m0.z, a0[3].z); a0[3].w = fmaf(s3, m0.w, a0[3].w);
            }
            if (t + T >= cmin) {
                a1[0].x = fmaf(s0, m1.x, a1[0].x); a1[0].y = fmaf(s0, m1.y, a1[0].y);
                a1[0].z = fmaf(s0, m1.z, a1[0].z); a1[0].w = fmaf(s0, m1.w, a1[0].w);
                a1[1].x = fmaf(s1, m1.x, a1[1].x); a1[1].y = fmaf(s1, m1.y, a1[1].y);
                a1[1].z = fmaf(s1, m1.z, a1[1].z); a1[1].w = fmaf(s1, m1.w, a1[1].w);
                a1[2].x = fmaf(s2, m1.x, a1[2].x); a1[2].y = fmaf(s2, m1.y, a1[2].y);
                a1[2].z = fmaf(s2, m1.z, a1[2].z); a1[2].w = fmaf(s2, m1.w, a1[2].w);
                a1[3].x = fmaf(s3, m1.x, a1[3].x); a1[3].y = fmaf(s3, m1.y, a1[3].y);
                a1[3].z = fmaf(s3, m1.z, a1[3].z); a1[3].w = fmaf(s3, m1.w, a1[3].w);
            }
            // --- prefetch next row (predicated on next step's active set) ---
            const int cminN = (i + 2) >> 2;
            const float4* nr4 = (const float4*)(g_maskT + (size_t)(i + 1) * NN);
            if (t >= cminN)     m0 = __ldg(nr4 + t);
            if (t + T >= cminN) m1 = __ldg(nr4 + t + T);

            // --- publish acc[g][i+1] for next step's decision ---
            const int ip = i + 1;
            const int cp = ip >> 2;
            const int comp = ip & 3;
            const int par = ip & 1;
            if (t == (cp & (T - 1))) {
                if (cp < T) {
                    if      (comp == 0) { pub[par][0]=a0[0].x; pub[par][1]=a0[1].x; pub[par][2]=a0[2].x; pub[par][3]=a0[3].x; }
                    else if (comp == 1) { pub[par][0]=a0[0].y; pub[par][1]=a0[1].y; pub[par][2]=a0[2].y; pub[par][3]=a0[3].y; }
                    else if (comp == 2) { pub[par][0]=a0[0].z; pub[par][1]=a0[1].z; pub[par][2]=a0[2].z; pub[par][3]=a0[3].z; }
                    else                { pub[par][0]=a0[0].w; pub[par][1]=a0[1].w; pub[par][2]=a0[2].w; pub[par][3]=a0[3].w; }
                } else {
                    if      (comp == 0) { pub[par][0]=a1[0].x; pub[par][1]=a1[1].x; pub[par][2]=a1[2].x; pub[par][3]=a1[3].x; }
                    else if (comp == 1) { pub[par][0]=a1[0].y; pub[par][1]=a1[1].y; pub[par][2]=a1[2].y; pub[par][3]=a1[3].y; }
                    else if (comp == 2) { pub[par][0]=a1[0].z; pub[par][1]=a1[1].z; pub[par][2]=a1[2].z; pub[par][3]=a1[3].z; }
                    else                { pub[par][0]=a1[0].w; pub[par][1]=a1[1].w; pub[par][2]=a1[2].w; pub[par][3]=a1[3].w; }
                }
            }
        }
        __syncthreads();
    }

    // --- x_hat epilogue: last column of mask is all zeros, so acc here equals
    // the reference's acc_prev exactly. sigmoid within ulp of ref (tol 1e-3).
    float* xh = out + (size_t)BB * NN;
#pragma unroll
    for (int g = 0; g < G; g++) {
        {
            int k0 = 4 * t;
            float4 h;
            h.x = xla_sigmoid(__fmul_rn(sw[k0 + 0], a0[g].x));
            h.y = xla_sigmoid(__fmul_rn(sw[k0 + 1], a0[g].y));
            h.z = xla_sigmoid(__fmul_rn(sw[k0 + 2], a0[g].z));
            h.w = xla_sigmoid(__fmul_rn(sw[k0 + 3], a0[g].w));
            *(float4*)(xh + (size_t)(bb + g) * NN + k0) = h;
        }
        {
            int k1 = 4 * (t + T);
            float4 h;
            h.x = xla_sigmoid(__fmul_rn(sw[k1 + 0], a1[g].x));
            h.y = xla_sigmoid(__fmul_rn(sw[k1 + 1], a1[g].y));
            h.z = xla_sigmoid(__fmul_rn(sw[k1 + 2], a1[g].z));
            h.w = xla_sigmoid(__fmul_rn(sw[k1 + 3], a1[g].w));
            *(float4*)(xh + (size_t)(bb + g) * NN + k1) = h;
        }
    }
}

extern "C" void kernel_launch(void* const* d_in, const int* in_sizes, int n_in,
                              void* d_out, int out_size)
{
    const float* weight = (const float*)d_in[0]; // [N]
    const float* mask   = (const float*)d_in[1]; // [N,N] row-major
    const float* u      = (const float*)d_in[2]; // [B,N]
    float* out = (float*)d_out;                  // [2*B*N]: sample then x_hat

    dim3 tb(32, 8), tg(NN / 32, NN / 32);
    transpose_kernel<<<tg, tb>>>(mask);
    bisect_kernel<<<(BB * NN + 255) / 256, 256>>>(u);
    hot_kernel<<<NCTA, T>>>(weight, out);
    (void)in_sizes; (void)n_in; (void)out_size;
}

// round 2
// speedup vs baseline: 2.1051x; 2.1051x over previous
#include <cuda_runtime.h>
#include <math.h>
#include <stdint.h>

#define NN 4096
#define BB 256
#define G  4             // batches per CTA
#define NCTA (BB / G)    // 64 CTAs
#define W  32            // block size (steps per block)
#define NB (NN / W)      // 128 blocks
#define NSEQ 128         // 4 seq warps
#define NBULK 512        // 16 bulk warps
#define T (NSEQ + NBULK) // 640 threads

// Scratch (static device globals: allocation-free rule)
__device__ float g_maskT[(size_t)NN * NN]; // maskT[i*N + k] = mask[k*N + i]
__device__ float g_thr[(size_t)BB * NN];   // thr[b*N + i]: threshold on x = w_i*acc

// ---------------- XLA-matching sigmoid (logistic -> 0.5 + 0.5*tanh(0.5x),
// tanh = Eigen generic_fast_tanh_float rational approx, as XLA EmitTanh) ----
__device__ __forceinline__ float xla_tanh(float x) {
    float ax = fabsf(x);
    if (ax < 0.0004f) return x;
    float xc = fminf(fmaxf(x, -7.90531110763549805f), 7.90531110763549805f);
    float x2 = xc * xc;
    float p = -2.76076847742355e-16f;
    p = fmaf(x2, p, 2.00018790482477e-13f);
    p = fmaf(x2, p, -8.60467152213735e-11f);
    p = fmaf(x2, p, 5.12229709037114e-08f);
    p = fmaf(x2, p, 1.48572235717979e-05f);
    p = fmaf(x2, p, 6.37261928875436e-04f);
    p = fmaf(x2, p, 4.89352455891786e-03f);
    p = xc * p;
    float q = fmaf(x2, 1.19825839466702e-06f, 1.18534705686654e-04f);
    q = fmaf(x2, q, 2.26843463243900e-03f);
    q = fmaf(x2, q, 4.89352518554385e-03f);
    return p / q;
}
__device__ __forceinline__ float xla_sigmoid(float x) {
    return fmaf(0.5f, xla_tanh(0.5f * x), 0.5f);
}

// ---------------- ordered-int float helpers ----------------
__device__ __forceinline__ unsigned f2o(float f) {
    unsigned b = __float_as_uint(f);
    return (b & 0x80000000u) ? ~b : (b | 0x80000000u);
}
__device__ __forceinline__ float o2f(unsigned o) {
    unsigned b = (o & 0x80000000u) ? (o & 0x7fffffffu) : ~o;
    return __uint_as_float(b);
}

// thr[b*N+i] = smallest fp32 x with (u[b,i] < sigmoid_xla(x)).
// v2: logit warm start + Newton + bracketed bisection (identical result to
// full-range bisection because the predicate is monotone and the bracket is
// verified: pred(lo)=false, pred(hi)=true before bisecting).
__global__ void bisect_kernel(const float* __restrict__ u) {
    int idx = blockIdx.x * blockDim.x + threadIdx.x;
    if (idx >= BB * NN) return;
    float uu = u[idx];
    const float SHI = xla_sigmoid(17.0f);   // saturated (clamp region)
    const float SLO = xla_sigmoid(-17.0f);
    float r;
    if (!(uu < SHI)) {
        r = INFINITY;              // never sample +1
    } else if (uu < SLO) {
        r = -INFINITY;             // always sample +1
    } else {
        // warm start: x0 ~ logit(u)
        float x0 = logf(uu) - logf(1.0f - uu);
        x0 = fminf(fmaxf(x0, -17.0f), 17.0f);
        // one Newton step on the exact function
        float s0 = xla_sigmoid(x0);
        float d0 = fmaxf(s0 * (1.0f - s0), 1e-12f);
        float x1 = x0 - (s0 - uu) / d0;
        x1 = fminf(fmaxf(x1, -17.0f), 17.0f);
        // bracket with margin; expand (rare) until verified
        float del = fmaf(fabsf(x1), 4e-6f, 5e-7f);
        float lo = x1 - del, hi = x1 + del;
        float dl = del;
        while (uu < xla_sigmoid(lo)) {            // need pred(lo)=false
            dl *= 4.0f; lo = x1 - dl;
            if (lo <= -17.0f) { lo = -17.0f; break; }  // pred(-17) false (uu>=SLO)
        }
        float dh = del;
        while (!(uu < xla_sigmoid(hi))) {         // need pred(hi)=true
            dh *= 4.0f; hi = x1 + dh;
            if (hi >= 17.0f) { hi = 17.0f; break; }    // pred(17) true (uu<SHI)
        }
        unsigned ilo = f2o(lo), ihi = f2o(hi);
        while (ihi - ilo > 1u) {
            unsigned mid = ilo + ((ihi - ilo) >> 1);
            if (uu < xla_sigmoid(o2f(mid))) ihi = mid; else ilo = mid;
        }
        r = o2f(ihi);
    }
    g_thr[idx] = r;
}

// ---------------- mask transpose (coalesced both sides) ----------------
__global__ void transpose_kernel(const float* __restrict__ mask) {
    __shared__ float tile[32][33];
    int x = blockIdx.x * 32 + threadIdx.x;
    int y0 = blockIdx.y * 32 + threadIdx.y;
#pragma unroll
    for (int j = 0; j < 32; j += 8)
        tile[threadIdx.y + j][threadIdx.x] = mask[(size_t)(y0 + j) * NN + x];
    __syncthreads();
    int x2 = blockIdx.y * 32 + threadIdx.x;
    int y2 = blockIdx.x * 32 + threadIdx.y;
#pragma unroll
    for (int j = 0; j < 32; j += 8)
        g_maskT[(size_t)(y2 + j) * NN + x2] = tile[threadIdx.x][threadIdx.y + j];
}

// ---------------- hot autoregressive kernel (blocked, W=32) ----------------
// 64 CTAs, 640 threads. Warps 0-3: sequential decision chain (warp g = batch g).
// Threads 128..639: bulk rank-32 updates; thread bt owns float4 chunks bt and
// bt+512 for all 4 batches (32 regs). Pipeline: iteration it runs S(it) on the
// seq warps concurrently with bulk(it-1) on the bulk warps. One barrier/iter.
// Exact-zero strict-triangle entries make unpredicated FMAs bit-exact no-ops.

#define FMA4(a4, sc, m4) \
    { (a4).x = fmaf((sc), (m4).x, (a4).x); (a4).y = fmaf((sc), (m4).y, (a4).y); \
      (a4).z = fmaf((sc), (m4).z, (a4).z); (a4).w = fmaf((sc), (m4).w, (a4).w); }

__global__ __launch_bounds__(T, 1) void hot_kernel(
    const float* __restrict__ weight, float* __restrict__ out)
{
    __shared__ float sw[NN];             // weights
    __shared__ float sbuf[2][W][G];      // s values, parity-buffered: [par][j][g]
    __shared__ float dbase[2][G][W];     // published diag columns: [par][g][i]
    const int tid = threadIdx.x;
    const int bb = blockIdx.x * G;

    for (int idx = tid; idx < NN; idx += T) sw[idx] = weight[idx];
    if (tid < 2 * G * W) ((float*)dbase)[tid] = 0.0f;

    // bulk accumulators
    float4 A0[G], A1[G];
#pragma unroll
    for (int g = 0; g < G; g++) {
        A0[g] = make_float4(0.f, 0.f, 0.f, 0.f);
        A1[g] = make_float4(0.f, 0.f, 0.f, 0.f);
    }
    const int bt = tid - NSEQ;           // bulk thread index (valid if tid>=128)
    const int c0 = bt, c1 = bt + NBULK;  // owned chunks
    const int g_seq = tid >> 5;          // seq warp id = batch
    const int lane = tid & 31;
    __syncthreads();

    for (int it = 0; it <= NB; ++it) {
        if (tid < NSEQ) {
            if (it < NB) {
                // ---- S(it): 32 sequential decisions for batch g_seq ----
                const int I = it * W;
                float acc = dbase[it & 1][g_seq][lane];
                if (it > 0) {
                    // fold rank-32 of previous block (superdiagonal couplings)
                    const float* derow = g_maskT + (size_t)(I - W) * NN + I + lane;
                    const float* sp = &sbuf[(it - 1) & 1][0][g_seq];
#pragma unroll 8
                    for (int j = 0; j < W; j++)
                        acc = fmaf(sp[4 * j], __ldg(derow + (size_t)j * NN), acc);
                }
                const float th = __ldg(g_thr + (size_t)(bb + g_seq) * NN + I + lane);
                const float wv = sw[I + lane];
                const float* mrow = g_maskT + (size_t)I * NN + I + lane;
                float dA[8], dB[8], mine = 0.0f;
#pragma unroll
                for (int q = 0; q < 8; q++) dA[q] = __ldg(mrow + (size_t)q * NN);
#pragma unroll
                for (int q = 0; q < 8; q++) dB[q] = __ldg(mrow + (size_t)(q + 8) * NN);
#define SSTEP(jj, dv) { \
    float x_ = __fmul_rn(wv, acc); \
    float sv_ = (x_ >= th) ? 1.0f : -1.0f; \
    float sj_ = __shfl_sync(0xffffffffu, sv_, (jj)); \
    mine = (lane == (jj)) ? sv_ : mine; \
    acc = fmaf(sj_, (dv), acc); }
#pragma unroll
                for (int q = 0; q < 8; q++) SSTEP(q, dA[q]);
#pragma unroll
                for (int q = 0; q < 8; q++) dA[q] = __ldg(mrow + (size_t)(q + 16) * NN);
#pragma unroll
                for (int q = 0; q < 8; q++) SSTEP(q + 8, dB[q]);
#pragma unroll
                for (int q = 0; q < 8; q++) dB[q] = __ldg(mrow + (size_t)(q + 24) * NN);
#pragma unroll
                for (int q = 0; q < 8; q++) SSTEP(q + 16, dA[q]);
#pragma unroll
                for (int q = 0; q < 8; q++) SSTEP(q + 24, dB[q]);
#undef SSTEP
                // publish decisions + write samples (coalesced 32-wide)
                sbuf[it & 1][lane][g_seq] = mine;
                out[(size_t)(bb + g_seq) * NN + I + lane] = mine;
            }
        } else if (it >= 1) {
            // ---- bulk(it-1): rank-32 update on owned chunks ----
            const int n = it - 1, I = n * W;
            const float* sp = &sbuf[n & 1][0][0];
            const bool act0 = (c0 >= 8 * n);   // c1 >= 512 >= 8n whenever act0
            const bool act1 = (c1 >= 8 * n);
            if (act0) {
                const float4* p0 = (const float4*)(g_maskT + (size_t)I * NN) + c0;
                const float4* p1 = p0 + NBULK;
#pragma unroll 4
                for (int j = 0; j < W; j++) {
                    float4 s4 = *(const float4*)(sp + 4 * j);
                    float4 m0 = __ldg(p0);
                    float4 m1 = __ldg(p1);
                    p0 += NN / 4; p1 += NN / 4;
                    FMA4(A0[0], s4.x, m0); FMA4(A0[1], s4.y, m0);
                    FMA4(A0[2], s4.z, m0); FMA4(A0[3], s4.w, m0);
                    FMA4(A1[0], s4.x, m1); FMA4(A1[1], s4.y, m1);
                    FMA4(A1[2], s4.z, m1); FMA4(A1[3], s4.w, m1);
                }
            } else if (act1) {
                const float4* p1 = (const float4*)(g_maskT + (size_t)I * NN) + c1;
#pragma unroll 4
                for (int j = 0; j < W; j++) {
                    float4 s4 = *(const float4*)(sp + 4 * j);
                    float4 m1 = __ldg(p1);
                    p1 += NN / 4;
                    FMA4(A1[0], s4.x, m1); FMA4(A1[1], s4.y, m1);
                    FMA4(A1[2], s4.z, m1); FMA4(A1[3], s4.w, m1);
                }
            }
            // publish diag columns for S(it+1): chunks [8(it+1), 8(it+1)+8)
            if (it + 1 < NB) {
                const int cd0 = (it + 1) * 8;
                if (c0 >= cd0 && c0 < cd0 + 8) {
                    const int off = 4 * (c0 - cd0);
#pragma unroll
                    for (int g = 0; g < G; g++)
                        *(float4*)&dbase[(it + 1) & 1][g][off] = A0[g];
                }
                if (c1 >= cd0 && c1 < cd0 + 8) {
                    const int off = 4 * (c1 - cd0);
#pragma unroll
                    for (int g = 0; g < G; g++)
                        *(float4*)&dbase[(it + 1) & 1][g][off] = A1[g];
                }
            }
        }
        __syncthreads();
    }

    // ---- x_hat epilogue: row N-1 of maskT is all-zero, so A == acc_prev ----
    if (tid >= NSEQ) {
        float* xh = out + (size_t)BB * NN;
        {
            const int k0 = 4 * c0;
#pragma unroll
            for (int g = 0; g < G; g++) {
                float4 a = A0[g], r;
                r.x = xla_sigmoid(__fmul_rn(sw[k0 + 0], a.x));
                r.y = xla_sigmoid(__fmul_rn(sw[k0 + 1], a.y));
                r.z = xla_sigmoid(__fmul_rn(sw[k0 + 2], a.z));
                r.w = xla_sigmoid(__fmul_rn(sw[k0 + 3], a.w));
                *(float4*)(xh + (size_t)(bb + g) * NN + k0) = r;
            }
        }
        {
            const int k1 = 4 * c1;
#pragma unroll
            for (int g = 0; g < G; g++) {
                float4 a = A1[g], r;
                r.x = xla_sigmoid(__fmul_rn(sw[k1 + 0], a.x));
                r.y = xla_sigmoid(__fmul_rn(sw[k1 + 1], a.y));
                r.z = xla_sigmoid(__fmul_rn(sw[k1 + 2], a.z));
                r.w = xla_sigmoid(__fmul_rn(sw[k1 + 3], a.w));
                *(float4*)(xh + (size_t)(bb + g) * NN + k1) = r;
            }
        }
    }
}

extern "C" void kernel_launch(void* const* d_in, const int* in_sizes, int n_in,
                              void* d_out, int out_size)
{
    const float* weight = (const float*)d_in[0]; // [N]
    const float* mask   = (const float*)d_in[1]; // [N,N] row-major
    const float* u      = (const float*)d_in[2]; // [B,N]
    float* out = (float*)d_out;                  // [2*B*N]: sample then x_hat

    dim3 tb(32, 8), tg(NN / 32, NN / 32);
    transpose_kernel<<<tg, tb>>>(mask);
    bisect_kernel<<<(BB * NN + 255) / 256, 256>>>(u);
    hot_kernel<<<NCTA, T>>>(weight, out);
    (void)in_sizes; (void)n_in; (void)out_size;
}

// round 3
// speedup vs baseline: 2.6758x; 1.2711x over previous
#include <cuda_runtime.h>
#include <math.h>
#include <stdint.h>

#define NN 4096
#define BB 256
#define G  4              // batches per cluster
#define W  32             // steps per block
#define NB (NN / W)       // 128 blocks
#define NSEQ 128          // 4 seq warps
#define NBULK 512         // 16 bulk warps
#define T (NSEQ + NBULK)  // 640 threads
#define NCTA 128          // 64 clusters x 2

// Scratch (static device globals: allocation-free rule)
__device__ float  g_maskT[(size_t)NN * NN]; // maskT[i*N + k] = mask[k*N + i]
__device__ float2 g_thrA[(size_t)BB * NN];  // {T, flip_bits}: s=+1 iff (acc>=T)^flip

// ---------------- XLA-matching sigmoid ----------------
__device__ __forceinline__ float xla_tanh(float x) {
    float ax = fabsf(x);
    if (ax < 0.0004f) return x;
    float xc = fminf(fmaxf(x, -7.90531110763549805f), 7.90531110763549805f);
    float x2 = xc * xc;
    float p = -2.76076847742355e-16f;
    p = fmaf(x2, p, 2.00018790482477e-13f);
    p = fmaf(x2, p, -8.60467152213735e-11f);
    p = fmaf(x2, p, 5.12229709037114e-08f);
    p = fmaf(x2, p, 1.48572235717979e-05f);
    p = fmaf(x2, p, 6.37261928875436e-04f);
    p = fmaf(x2, p, 4.89352455891786e-03f);
    p = xc * p;
    float q = fmaf(x2, 1.19825839466702e-06f, 1.18534705686654e-04f);
    q = fmaf(x2, q, 2.26843463243900e-03f);
    q = fmaf(x2, q, 4.89352518554385e-03f);
    return p / q;
}
__device__ __forceinline__ float xla_sigmoid(float x) {
    return fmaf(0.5f, xla_tanh(0.5f * x), 0.5f);
}

// ---------------- ordered-int float helpers ----------------
__device__ __forceinline__ unsigned f2o(float f) {
    unsigned b = __float_as_uint(f);
    return (b & 0x80000000u) ? ~b : (b | 0x80000000u);
}
__device__ __forceinline__ float o2f(unsigned o) {
    unsigned b = (o & 0x80000000u) ? (o & 0x7fffffffu) : ~o;
    return __uint_as_float(b);
}

// Per (b,i): stage 1 finds xT = smallest fp32 x with u < sigmoid_xla(x)
// (warm-start + verified-bracket bisection). Stage 2 converts to an
// acc-space threshold using the EXACT monotone predicate rn(w*acc) >= xT:
// s=+1  iff  (acc >= T) XOR flip. Bit-identical decisions to the reference.
__global__ void thr_kernel(const float* __restrict__ u,
                           const float* __restrict__ weight) {
    int idx = blockIdx.x * blockDim.x + threadIdx.x;
    if (idx >= BB * NN) return;
    int i = idx & (NN - 1);
    float uu = u[idx];
    float w = weight[i];

    const float SHI = xla_sigmoid(17.0f);
    const float SLO = xla_sigmoid(-17.0f);
    float xT;
    if (!(uu < SHI)) {
        xT = INFINITY;
    } else if (uu < SLO) {
        xT = -INFINITY;
    } else {
        float x0 = logf(uu) - logf(1.0f - uu);
        x0 = fminf(fmaxf(x0, -17.0f), 17.0f);
        float s0 = xla_sigmoid(x0);
        float d0 = fmaxf(s0 * (1.0f - s0), 1e-12f);
        float x1 = x0 - (s0 - uu) / d0;
        x1 = fminf(fmaxf(x1, -17.0f), 17.0f);
        float del = fmaf(fabsf(x1), 4e-6f, 5e-7f);
        float lo = x1 - del, hi = x1 + del;
        float dl = del;
        while (uu < xla_sigmoid(lo)) {
            dl *= 4.0f; lo = x1 - dl;
            if (lo <= -17.0f) { lo = -17.0f; break; }
        }
        float dh = del;
        while (!(uu < xla_sigmoid(hi))) {
            dh *= 4.0f; hi = x1 + dh;
            if (hi >= 17.0f) { hi = 17.0f; break; }
        }
        unsigned ilo = f2o(lo), ihi = f2o(hi);
        while (ihi - ilo > 1u) {
            unsigned mid = ilo + ((ihi - ilo) >> 1);
            if (uu < xla_sigmoid(o2f(mid))) ihi = mid; else ilo = mid;
        }
        xT = o2f(ihi);
    }

    float Tv; unsigned flip = 0u;
    if (xT == -INFINITY) {
        Tv = -INFINITY;                         // always +1
    } else if (xT == INFINITY) {
        Tv = INFINITY;                          // never +1
    } else if (w > 0.0f) {
        // smallest acc with rn(w*acc) >= xT (monotone non-decreasing)
        unsigned lo = f2o(-INFINITY), hi = f2o(INFINITY);
        while (hi - lo > 1u) {
            unsigned mid = lo + ((hi - lo) >> 1);
            if (__fmul_rn(w, o2f(mid)) >= xT) hi = mid; else lo = mid;
        }
        Tv = o2f(hi);
    } else if (w < 0.0f) {
        // predicate non-increasing: s=+1 iff acc <= A*. Find smallest acc
        // with predicate FALSE -> T; s = !(acc >= T).
        unsigned lo = f2o(-INFINITY), hi = f2o(INFINITY);
        while (hi - lo > 1u) {
            unsigned mid = lo + ((hi - lo) >> 1);
            if (!(__fmul_rn(w, o2f(mid)) >= xT)) hi = mid; else lo = mid;
        }
        Tv = o2f(hi);
        flip = 0xffffffffu;
    } else {
        // w == +/-0: x = +/-0, compares as 0
        Tv = (0.0f >= xT) ? -INFINITY : INFINITY;
    }
    g_thrA[idx] = make_float2(Tv, __uint_as_float(flip));
}

// ---------------- mask transpose ----------------
__global__ void transpose_kernel(const float* __restrict__ mask) {
    __shared__ float tile[32][33];
    int x = blockIdx.x * 32 + threadIdx.x;
    int y0 = blockIdx.y * 32 + threadIdx.y;
#pragma unroll
    for (int j = 0; j < 32; j += 8)
        tile[threadIdx.y + j][threadIdx.x] = mask[(size_t)(y0 + j) * NN + x];
    __syncthreads();
    int x2 = blockIdx.y * 32 + threadIdx.x;
    int y2 = blockIdx.x * 32 + threadIdx.y;
#pragma unroll
    for (int j = 0; j < 32; j += 8)
        g_maskT[(size_t)(y2 + j) * NN + x2] = tile[threadIdx.x][threadIdx.y + j];
}

// ---------------- cluster / ptx helpers ----------------
__device__ __forceinline__ unsigned smem_u32(const void* p) {
    unsigned r;
    asm("{ .reg .u64 t; cvta.to.shared.u64 t, %1; cvt.u32.u64 %0, t; }"
        : "=r"(r) : "l"(p));
    return r;
}
__device__ __forceinline__ void st_peer64(unsigned laddr, unsigned peer,
                                          unsigned long long v) {
    unsigned r;
    asm("mapa.shared::cluster.u32 %0, %1, %2;" : "=r"(r) : "r"(laddr), "r"(peer));
    asm volatile("st.shared::cluster.b64 [%0], %1;" :: "r"(r), "l"(v) : "memory");
}
__device__ __forceinline__ void cluster_sync_() {
    asm volatile("barrier.cluster.arrive.aligned;" ::: "memory");
    asm volatile("barrier.cluster.wait.aligned;" ::: "memory");
}
__device__ __forceinline__ unsigned ctarank_() {
    unsigned r; asm("mov.u32 %0, %%cluster_ctarank;" : "=r"(r)); return r;
}
__device__ __forceinline__ void fma2_(unsigned long long& d,
                                      unsigned long long a,
                                      unsigned long long b) {
    asm("fma.rn.f32x2 %0, %1, %2, %0;" : "+l"(d) : "l"(a), "l"(b));
}

// ---------------- hot kernel: cluster-2 split-k, blocked W=32 ----------------
// 64 clusters x 2 CTAs. Cluster c owns batches 4c..4c+3; each CTA owns
// alternating 128B column groups (8 float4 chunks). Warps 0-3: redundant
// sequential decision chain (speculative, sign-mask form). 16 bulk warps:
// rank-32 f32x2 updates, thread bt owns one float4 chunk for all 4 batches.
__global__ __launch_bounds__(T, 1) __cluster_dims__(2, 1, 1)
void hot_kernel(const float* __restrict__ weight, float* __restrict__ out)
{
    __shared__ __align__(16) float2 sbuf[2][W][G];   // duplicated {s,s}
    __shared__ __align__(16) float  dbase[2][G][W];  // diag acc columns
    __shared__ float  ds[2][W][W];                   // diag mask tile
    __shared__ float  es[2][W][W];                   // superdiag mask tile
    __shared__ __align__(16) float2 sthrf[2][G][W];  // {T, flip}

    const int tid = threadIdx.x;
    const unsigned rank = ctarank_();
    const int bb = (blockIdx.x >> 1) * G;
    const int lane = tid & 31;

    // bulk chunk ownership: 128B-granular interleave between the 2 CTAs
    const int bt = tid - NSEQ;
    const int cg = (bt >> 3) * 16 + (int)rank * 8 + (bt & 7);
    unsigned long long A[8];   // acc: [g][half], 2 floats each
#pragma unroll
    for (int q = 0; q < 8; q++) A[q] = 0ull;

    // preload block-0 tiles
    for (int idx = tid; idx < W * W; idx += T) {
        int r = idx >> 5, c = idx & 31;
        ds[0][r][c] = __ldg(g_maskT + (size_t)r * NN + c);
    }
    if (tid < 2 * G * W) ((float*)dbase)[tid] = 0.0f;
    if (tid < G * W) {
        int g = tid >> 5, l = tid & 31;
        sthrf[0][g][l] = __ldg(g_thrA + (size_t)(bb + g) * NN + l);
    }
    cluster_sync_();

    for (int it = 0; it <= NB; ++it) {
        const int par = it & 1;
        if (tid < NSEQ) {
            if (it < NB) {
                const int I = it * W;
                const int g_seq = tid >> 5;
                float acc = dbase[par][g_seq][lane];
                if (it > 0) {
#pragma unroll
                    for (int j = 0; j < W; j++)
                        acc = fmaf(sbuf[par ^ 1][j][g_seq].x, es[par][j][lane], acc);
                }
                float2 tf = sthrf[par][g_seq][lane];
                const float t = tf.x;
                const unsigned fl = __float_as_uint(tf.y);
                unsigned mrecv, mine = 0u;
                {
                    float c = acc - t;
                    unsigned mm = ((unsigned)(__float_as_int(c) >> 31)) ^ fl;
                    mine = (lane == 0) ? mm : mine;
                    mrecv = __shfl_sync(0xffffffffu, mm, 0);
                }
#pragma unroll
                for (int j = 1; j < W; j++) {
                    float d = ds[par][j - 1][lane];
                    float accP = acc + d;                 // == fmaf(+1,d,acc)
                    float accM = acc - d;                 // == fmaf(-1,d,acc)
                    unsigned mP = ((unsigned)(__float_as_int(accP - t) >> 31)) ^ fl;
                    unsigned mM = ((unsigned)(__float_as_int(accM - t) >> 31)) ^ fl;
                    unsigned mx = mP ^ mM;
                    unsigned ab = (__float_as_uint(accP) & ~mrecv) |
                                  (__float_as_uint(accM) & mrecv);
                    acc = __uint_as_float(ab);
                    unsigned mm = mP ^ (mrecv & mx);
                    mine = (lane == j) ? mm : mine;
                    mrecv = __shfl_sync(0xffffffffu, mm, j);
                }
                float sfl = __uint_as_float(0x3f800000u | (mine & 0x80000000u));
                sbuf[par][lane][g_seq] = make_float2(sfl, sfl);
                if (rank == 0)
                    out[(size_t)(bb + g_seq) * NN + I + lane] = sfl;
                // stage tiles for block it+1
                if (it + 1 < NB) {
                    const int I2 = (it + 1) * W;
                    for (int idx = tid; idx < W * W; idx += NSEQ) {
                        int r = idx >> 5, c = idx & 31;
                        ds[par ^ 1][r][c] = __ldg(g_maskT + (size_t)(I2 + r) * NN + I2 + c);
                        es[par ^ 1][r][c] = __ldg(g_maskT + (size_t)(I2 - W + r) * NN + I2 + c);
                    }
                    {
                        int g = tid >> 5, l = tid & 31;
                        sthrf[par ^ 1][g][l] =
                            __ldg(g_thrA + (size_t)(bb + g) * NN + I2 + l);
                    }
                }
            }
        } else if (it >= 1) {
            const int n = it - 1, I = n * W;
            if (4 * cg + 3 > I) {
                const int pj = par ^ 1;  // (it-1)&1
                const ulonglong2* mp = (const ulonglong2*)(g_maskT + (size_t)I * NN) + cg;
#pragma unroll 4
                for (int j = 0; j < W; j++) {
                    ulonglong2 m2 = __ldg(mp); mp += NN / 4;
                    ulonglong2 s01 = *(const ulonglong2*)&sbuf[pj][j][0];
                    ulonglong2 s23 = *(const ulonglong2*)&sbuf[pj][j][2];
                    fma2_(A[0], s01.x, m2.x); fma2_(A[1], s01.x, m2.y);
                    fma2_(A[2], s01.y, m2.x); fma2_(A[3], s01.y, m2.y);
                    fma2_(A[4], s23.x, m2.x); fma2_(A[5], s23.x, m2.y);
                    fma2_(A[6], s23.y, m2.x); fma2_(A[7], s23.y, m2.y);
                }
            }
            // publish diag columns for S(it+1) to BOTH CTAs' dbase
            if (it + 1 < NB) {
                const int cd0 = (it + 1) * 8;
                if (cg >= cd0 && cg < cd0 + 8) {
                    const int off = (cg - cd0) * 4;
                    const int p2 = par ^ 1;  // (it+1)&1
#pragma unroll
                    for (int g = 0; g < G; g++) {
                        unsigned long long* dst =
                            (unsigned long long*)&dbase[p2][g][off];
                        dst[0] = A[2 * g]; dst[1] = A[2 * g + 1];
                        unsigned la = smem_u32(dst);
                        st_peer64(la, rank ^ 1u, A[2 * g]);
                        st_peer64(la + 8, rank ^ 1u, A[2 * g + 1]);
                    }
                }
            }
        }
        cluster_sync_();
    }

    // ---- x_hat epilogue: row N-1 of maskT is all-zero, so A == acc_prev ----
    if (tid >= NSEQ) {
        float* xh = out + (size_t)BB * NN;
        float4 wv = __ldg((const float4*)weight + cg);
#pragma unroll
        for (int g = 0; g < G; g++) {
            float a0 = __uint_as_float((unsigned)(A[2 * g] & 0xffffffffu));
            float a1 = __uint_as_float((unsigned)(A[2 * g] >> 32));
            float a2 = __uint_as_float((unsigned)(A[2 * g + 1] & 0xffffffffu));
            float a3 = __uint_as_float((unsigned)(A[2 * g + 1] >> 32));
            float4 r;
            r.x = xla_sigmoid(__fmul_rn(wv.x, a0));
            r.y = xla_sigmoid(__fmul_rn(wv.y, a1));
            r.z = xla_sigmoid(__fmul_rn(wv.z, a2));
            r.w = xla_sigmoid(__fmul_rn(wv.w, a3));
            *(float4*)(xh + (size_t)(bb + g) * NN + 4 * cg) = r;
        }
    }
}

extern "C" void kernel_launch(void* const* d_in, const int* in_sizes, int n_in,
                              void* d_out, int out_size)
{
    const float* weight = (const float*)d_in[0]; // [N]
    const float* mask   = (const float*)d_in[1]; // [N,N] row-major
    const float* u      = (const float*)d_in[2]; // [B,N]
    float* out = (float*)d_out;                  // [2*B*N]: sample then x_hat

    dim3 tb(32, 8), tg(NN / 32, NN / 32);
    transpose_kernel<<<tg, tb>>>(mask);
    thr_kernel<<<(BB * NN + 255) / 256, 256>>>(u, weight);
    hot_kernel<<<NCTA, T>>>(weight, out);
    (void)in_sizes; (void)n_in; (void)out_size;
}